// round 8
// baseline (speedup 1.0000x reference)
#include <cuda_runtime.h>

// preds:   (8, 6, 4, 512, 512) fp32  -> 201,326,592 floats
// targets: (8, 6,    512, 512) ints  -> 12,582,912 values (int32 or int64-LE, detected at runtime)
// out = (1/8) * sum_{n,s,h,w} ( logsumexp_c preds[n,s,:,h,w] - preds[n,s,t,h,w] )
//
// Measured history:
//   R4: two kernels, PXT=4, 12288 blocks -> 41.5us (best)
//   R5: fused fence+counter              -> 43.5us (regression)
//   R6: PXT=8                            -> 43.1us (regression)
//   R7: PDL + hoisted loads              -> 43.0us (regression)
// This round: R4 structure, but PERSISTENT grid (148 SMs x 8 blocks, grid-stride)
// to eliminate the 10.4-wave quantization tail in the main kernel.

#define HW          262144               // 512*512 = 2^18
#define CHW         (4 * HW)             // 2^20
#define TOTAL_PX    12582912             // 48 * HW
#define TOTAL_QUADS (TOTAL_PX / 4)       // 3,145,728
#define THREADS     256
#define NSM         148
#define BLK_PER_SM  8
#define NBLOCKS     (NSM * BLK_PER_SM)   // 1184
#define GSIZE       (NBLOCKS * THREADS)  // 303,104 threads

static __device__ double g_acc = 0.0;    // reset by finalize -> graph-replay deterministic

__device__ __forceinline__ float ce_pixel(float a, float b, float c, float d, int t) {
    float m  = fmaxf(fmaxf(a, b), fmaxf(c, d));
    float s  = __expf(a - m) + __expf(b - m) + __expf(c - m) + __expf(d - m);
    float xt = (t == 0) ? a : (t == 1) ? b : (t == 2) ? c : d;
    return m + __logf(s) - xt;
}

__device__ __forceinline__ float ce_quad_i32(const float* __restrict__ preds,
                                             const int* __restrict__ tgt, int q) {
    int p0 = q << 2;
    int ns = p0 >> 18;
    int hw = p0 & (HW - 1);
    const float* base = preds + (long long)ns * CHW + hw;

    float4 v0 = *reinterpret_cast<const float4*>(base);
    float4 v1 = *reinterpret_cast<const float4*>(base + HW);
    float4 v2 = *reinterpret_cast<const float4*>(base + 2 * HW);
    float4 v3 = *reinterpret_cast<const float4*>(base + 3 * HW);
    int4   t  = *reinterpret_cast<const int4*>(tgt + p0);

    return ce_pixel(v0.x, v1.x, v2.x, v3.x, t.x)
         + ce_pixel(v0.y, v1.y, v2.y, v3.y, t.y)
         + ce_pixel(v0.z, v1.z, v2.z, v3.z, t.z)
         + ce_pixel(v0.w, v1.w, v2.w, v3.w, t.w);
}

__device__ __forceinline__ float ce_quad_i64(const float* __restrict__ preds,
                                             const int* __restrict__ tgt, int q) {
    int p0 = q << 2;
    int ns = p0 >> 18;
    int hw = p0 & (HW - 1);
    const float* base = preds + (long long)ns * CHW + hw;

    float4 v0 = *reinterpret_cast<const float4*>(base);
    float4 v1 = *reinterpret_cast<const float4*>(base + HW);
    float4 v2 = *reinterpret_cast<const float4*>(base + 2 * HW);
    float4 v3 = *reinterpret_cast<const float4*>(base + 3 * HW);
    const int4* tp = reinterpret_cast<const int4*>(tgt + 2LL * p0);
    int4 ta = tp[0], tb = tp[1];                 // low words of int64-LE

    return ce_pixel(v0.x, v1.x, v2.x, v3.x, ta.x)
         + ce_pixel(v0.y, v1.y, v2.y, v3.y, ta.z)
         + ce_pixel(v0.z, v1.z, v2.z, v3.z, tb.x)
         + ce_pixel(v0.w, v1.w, v2.w, v3.w, tb.z);
}

__global__ void __launch_bounds__(THREADS, BLK_PER_SM)
nims_ce_main_kernel(const float* __restrict__ preds,
                    const int* __restrict__ tgt) {
    __shared__ int   s_stride2;                 // 1 if targets are int64 (LE), else 0
    __shared__ float warp_sums[THREADS / 32];

    int lane = threadIdx.x & 31;
    int wid  = threadIdx.x >> 5;

    // Per-block dtype probe: int64-LE values in [0,4) => every odd 32-bit word is 0.
    if (wid == 0) {
        int w = tgt[2 * lane + 1];
        unsigned nz = __ballot_sync(0xFFFFFFFF, w != 0);
        if (lane == 0) s_stride2 = (nz == 0u);
    }
    __syncthreads();

    int gtid = blockIdx.x * THREADS + threadIdx.x;

    float local = 0.0f;
    if (!s_stride2) {
        for (int q = gtid; q < TOTAL_QUADS; q += GSIZE)
            local += ce_quad_i32(preds, tgt, q);
    } else {
        for (int q = gtid; q < TOTAL_QUADS; q += GSIZE)
            local += ce_quad_i64(preds, tgt, q);
    }

    #pragma unroll
    for (int off = 16; off > 0; off >>= 1)
        local += __shfl_xor_sync(0xFFFFFFFF, local, off);

    if (lane == 0) warp_sums[wid] = local;
    __syncthreads();

    if (wid == 0) {
        float v = (lane < THREADS / 32) ? warp_sums[lane] : 0.0f;
        #pragma unroll
        for (int off = 4; off > 0; off >>= 1)
            v += __shfl_xor_sync(0xFFFFFFFF, v, off);
        if (lane == 0)
            atomicAdd(&g_acc, (double)v);       // unused result -> REDG (no return wait)
    }
}

__global__ void nims_ce_finalize_kernel(float* __restrict__ out) {
    out[0] = (float)(g_acc * (1.0 / 8.0));   // mean over N=8
    g_acc = 0.0;                              // reset for the next graph replay
}

extern "C" void kernel_launch(void* const* d_in, const int* in_sizes, int n_in,
                              void* d_out, int out_size) {
    // Role selection by size: preds is strictly the larger buffer under any
    // unit convention (elements or bytes).
    int preds_idx = 0, tgt_idx = 1;
    if (n_in >= 2 && (long long)in_sizes[1] > (long long)in_sizes[0]) {
        preds_idx = 1; tgt_idx = 0;
    }

    const float* preds = (const float*)d_in[preds_idx];
    const int*   tgt   = (const int*)d_in[tgt_idx];
    float*       out   = (float*)d_out;

    nims_ce_main_kernel<<<NBLOCKS, THREADS>>>(preds, tgt);
    nims_ce_finalize_kernel<<<1, 1>>>(out);
}

// round 9
// speedup vs baseline: 1.0821x; 1.0821x over previous
#include <cuda_runtime.h>

// preds:   (8, 6, 4, 512, 512) fp32  -> 201,326,592 floats
// targets: (8, 6,    512, 512) int32 -> 12,582,912 values in [0,4)
//   (int32 established by evidence: R1's 2x-stride int64 reads crashed OOB,
//    and all probe-guided runs since returned rel_err=0.0 via the int32 path.)
// out = (1/8) * sum_{n,s,h,w} ( logsumexp_c preds[n,s,:,h,w] - preds[n,s,t,h,w] )
//
// Measured history:
//   R4: two kernels, PXT=4, 12288 blocks, dtype probe -> 41.5us (best)
//   R5 fused-fence 43.5 / R6 PXT=8 43.1 / R7 PDL 43.0 / R8 persistent 45.2 (all regressions)
// This round: R4 exactly, minus the per-block dtype probe (L2 round-trip +
// ballot + __syncthreads removed from every block's issue prologue).

#define HW        262144                 // 512*512 = 2^18
#define CHW       (4 * HW)               // 2^20
#define TOTAL_PX  12582912               // 48 * HW
#define THREADS   256
#define PXT       4                      // pixels per thread (measured optimum)
#define NBLOCKS   (TOTAL_PX / (THREADS * PXT))   // 12288 exactly

static __device__ double g_acc = 0.0;    // reset by finalize -> graph-replay deterministic

__device__ __forceinline__ float ce_pixel(float a, float b, float c, float d, int t) {
    float m  = fmaxf(fmaxf(a, b), fmaxf(c, d));
    float s  = __expf(a - m) + __expf(b - m) + __expf(c - m) + __expf(d - m);
    float xt = (t == 0) ? a : (t == 1) ? b : (t == 2) ? c : d;
    return m + __logf(s) - xt;
}

__global__ void __launch_bounds__(THREADS)
nims_ce_main_kernel(const float* __restrict__ preds,
                    const int* __restrict__ tgt) {
    __shared__ float warp_sums[THREADS / 32];

    int p0 = (blockIdx.x * THREADS + threadIdx.x) * PXT;   // < TOTAL_PX, multiple of 4
    int ns = p0 >> 18;
    int hw = p0 & (HW - 1);
    const float* base = preds + (long long)ns * CHW + hw;

    // 5 independent, coalesced 16B loads issue back-to-back (max MLP).
    float4 v0 = *reinterpret_cast<const float4*>(base);
    float4 v1 = *reinterpret_cast<const float4*>(base + HW);
    float4 v2 = *reinterpret_cast<const float4*>(base + 2 * HW);
    float4 v3 = *reinterpret_cast<const float4*>(base + 3 * HW);
    int4   t  = *reinterpret_cast<const int4*>(tgt + p0);

    float local = ce_pixel(v0.x, v1.x, v2.x, v3.x, t.x)
                + ce_pixel(v0.y, v1.y, v2.y, v3.y, t.y)
                + ce_pixel(v0.z, v1.z, v2.z, v3.z, t.z)
                + ce_pixel(v0.w, v1.w, v2.w, v3.w, t.w);

    #pragma unroll
    for (int off = 16; off > 0; off >>= 1)
        local += __shfl_xor_sync(0xFFFFFFFF, local, off);

    int lane = threadIdx.x & 31;
    int wid  = threadIdx.x >> 5;
    if (lane == 0) warp_sums[wid] = local;
    __syncthreads();

    if (wid == 0) {
        float v = (lane < THREADS / 32) ? warp_sums[lane] : 0.0f;
        #pragma unroll
        for (int off = 4; off > 0; off >>= 1)
            v += __shfl_xor_sync(0xFFFFFFFF, v, off);
        if (lane == 0)
            atomicAdd(&g_acc, (double)v);      // unused result -> REDG (no return wait)
    }
}

__global__ void nims_ce_finalize_kernel(float* __restrict__ out) {
    out[0] = (float)(g_acc * (1.0 / 8.0));   // mean over N=8
    g_acc = 0.0;                              // reset for the next graph replay
}

extern "C" void kernel_launch(void* const* d_in, const int* in_sizes, int n_in,
                              void* d_out, int out_size) {
    // Role selection by size: preds is strictly the larger buffer under any
    // unit convention (elements or bytes).
    int preds_idx = 0, tgt_idx = 1;
    if (n_in >= 2 && (long long)in_sizes[1] > (long long)in_sizes[0]) {
        preds_idx = 1; tgt_idx = 0;
    }

    const float* preds = (const float*)d_in[preds_idx];
    const int*   tgt   = (const int*)d_in[tgt_idx];
    float*       out   = (float*)d_out;

    nims_ce_main_kernel<<<NBLOCKS, THREADS>>>(preds, tgt);
    nims_ce_finalize_kernel<<<1, 1>>>(out);
}

// round 10
// speedup vs baseline: 1.0887x; 1.0062x over previous
#include <cuda_runtime.h>

// preds:   (8, 6, 4, 512, 512) fp32  -> 201,326,592 floats
// targets: (8, 6,    512, 512) int32 -> 12,582,912 values in [0,4)
// out = (1/8) * sum_{n,s,h,w} ( logsumexp_c preds[n,s,:,h,w] - preds[n,s,t,h,w] )
//
// Measured history:
//   R4/R9: two kernels, PXT=4, 12288 blocks -> 41.5/41.7us (best; main ~36us = 7.0TB/s)
//   R5: fused via __threadfence+2 dep atomics -> 43.5us (CCTL.IVALL + atomic-chain tail)
//   R6 PXT=8 / R7 PDL / R8 persistent -> all regressions
// This round: single fused kernel, but the epilogue is ONE red.relaxed.f64
// (no return-wait) + ONE atom.acq_rel.u32 counter (release publishes the red;
// acquire in the last block makes all reds visible). No fence, no L1 flush.

#define HW        262144                 // 512*512 = 2^18
#define CHW       (4 * HW)               // 2^20
#define TOTAL_PX  12582912               // 48 * HW
#define THREADS   256
#define PXT       4                      // pixels per thread (measured optimum)
#define NBLOCKS   (TOTAL_PX / (THREADS * PXT))   // 12288 exactly

static __device__ double       g_acc     = 0.0;   // reset by last block each run
static __device__ unsigned int g_counter = 0u;    // reset by last block each run

__device__ __forceinline__ float ce_pixel(float a, float b, float c, float d, int t) {
    float m  = fmaxf(fmaxf(a, b), fmaxf(c, d));
    float s  = __expf(a - m) + __expf(b - m) + __expf(c - m) + __expf(d - m);
    float xt = (t == 0) ? a : (t == 1) ? b : (t == 2) ? c : d;
    return m + __logf(s) - xt;
}

__global__ void __launch_bounds__(THREADS)
nims_ce_fused_kernel(const float* __restrict__ preds,
                     const int* __restrict__ tgt,
                     float* __restrict__ out) {
    __shared__ float warp_sums[THREADS / 32];

    int p0 = (blockIdx.x * THREADS + threadIdx.x) * PXT;   // < TOTAL_PX, multiple of 4
    int ns = p0 >> 18;
    int hw = p0 & (HW - 1);
    const float* base = preds + (long long)ns * CHW + hw;

    // 5 independent, coalesced 16B loads issue back-to-back (max MLP).
    float4 v0 = *reinterpret_cast<const float4*>(base);
    float4 v1 = *reinterpret_cast<const float4*>(base + HW);
    float4 v2 = *reinterpret_cast<const float4*>(base + 2 * HW);
    float4 v3 = *reinterpret_cast<const float4*>(base + 3 * HW);
    int4   t  = *reinterpret_cast<const int4*>(tgt + p0);

    float local = ce_pixel(v0.x, v1.x, v2.x, v3.x, t.x)
                + ce_pixel(v0.y, v1.y, v2.y, v3.y, t.y)
                + ce_pixel(v0.z, v1.z, v2.z, v3.z, t.z)
                + ce_pixel(v0.w, v1.w, v2.w, v3.w, t.w);

    #pragma unroll
    for (int off = 16; off > 0; off >>= 1)
        local += __shfl_xor_sync(0xFFFFFFFF, local, off);

    int lane = threadIdx.x & 31;
    int wid  = threadIdx.x >> 5;
    if (lane == 0) warp_sums[wid] = local;
    __syncthreads();

    if (wid == 0) {
        float v = (lane < THREADS / 32) ? warp_sums[lane] : 0.0f;
        #pragma unroll
        for (int off = 4; off > 0; off >>= 1)
            v += __shfl_xor_sync(0xFFFFFFFF, v, off);

        if (lane == 0) {
            // Fire-and-forget relaxed reduction (REDG, no return wait).
            asm volatile("red.relaxed.gpu.global.add.f64 [%0], %1;"
                         :: "l"(&g_acc), "d"((double)v) : "memory");

            // acq_rel counter RMW: release publishes the red above; the block
            // that reads old == NBLOCKS-1 acquires every prior release.
            unsigned old;
            asm volatile("atom.acq_rel.gpu.global.add.u32 %0, [%1], %2;"
                         : "=r"(old) : "l"(&g_counter), "r"(1u) : "memory");

            if (old == NBLOCKS - 1) {
                // All reds are visible (acquired). Read-and-reset for replay.
                unsigned long long bits;
                asm volatile("atom.relaxed.gpu.global.exch.b64 %0, [%1], %2;"
                             : "=l"(bits) : "l"(&g_acc), "l"(0ULL) : "memory");
                double acc = __longlong_as_double((long long)bits);
                out[0] = (float)(acc * (1.0 / 8.0));        // mean over N=8
                asm volatile("st.relaxed.gpu.global.u32 [%0], %1;"
                             :: "l"(&g_counter), "r"(0u) : "memory");
            }
        }
    }
}

extern "C" void kernel_launch(void* const* d_in, const int* in_sizes, int n_in,
                              void* d_out, int out_size) {
    // Role selection by size: preds is strictly the larger buffer under any
    // unit convention (elements or bytes).
    int preds_idx = 0, tgt_idx = 1;
    if (n_in >= 2 && (long long)in_sizes[1] > (long long)in_sizes[0]) {
        preds_idx = 1; tgt_idx = 0;
    }

    const float* preds = (const float*)d_in[preds_idx];
    const int*   tgt   = (const int*)d_in[tgt_idx];
    float*       out   = (float*)d_out;

    nims_ce_fused_kernel<<<NBLOCKS, THREADS>>>(preds, tgt, out);
}